// round 2
// baseline (speedup 1.0000x reference)
#include <cuda_runtime.h>

// EMA: y_t = (1-w)*y_{t-1} + w*x_t, per channel w, constant over t.
// Single-pass decoupled-lookback scan:
//   - chunk T into L=32, one block per (b, chunk), one thread per channel
//   - phase A: stash chunk in registers, compute zero-start aggregate e_k
//   - publish {flag,value} packed in one 64-bit word (atomic store, no fence)
//   - lookback: batched (8-wide) predecessor reads; prefix short-circuit
//   - phase C: replay from registers, stream the outputs
// Traffic ~ read-once + write-once + ~24MB bookkeeping => HBM-bound.

#define TT   8192
#define CC   256
#define LL   32
#define NCH  (TT / LL)   // 256 chunks per batch row
#define MAXB 16

// packed carry: high 32 bits = flag (0 empty / 1 aggregate / 2 inclusive prefix),
// low 32 bits = float payload. 8MB scratch, zeroed every launch.
__device__ unsigned long long g_carry[MAXB * NCH * CC];

__global__ void ema_clear_kernel() {
    int i = blockIdx.x * blockDim.x + threadIdx.x;
    g_carry[i] = 0ULL;
}

__global__ __launch_bounds__(CC, 4) void ema_scan_kernel(
    const float* __restrict__ x,
    const float* __restrict__ y0,
    const float* __restrict__ smooth,
    float* __restrict__ out)
{
    const int k = blockIdx.x % NCH;   // chunk index (fast dim -> preds have lower bid)
    const int b = blockIdx.x / NCH;   // batch index
    const int c = threadIdx.x;        // channel

    const float w = fminf(fmaxf(smooth[c], 0.0f), 1.0f);
    const float a = 1.0f - w;

    // ---- Phase A: load chunk into registers, compute zero-start aggregate ----
    const float* xp = x + ((b * TT + k * LL) * CC + c);
    float xs[LL];
#pragma unroll
    for (int i = 0; i < LL; i++) xs[i] = __ldcs(xp + i * CC);

    float e = 0.0f;
#pragma unroll
    for (int i = 0; i < LL; i++) e = fmaf(a, e, w * xs[i]);

    // A_L = a^32 via 5 squarings
    float A2 = a * a;
    float A4 = A2 * A2;
    float A8 = A4 * A4;
    float A16 = A8 * A8;
    const float AL = A16 * A16;

    volatile unsigned long long* cb = g_carry + (b * NCH) * CC;

    // publish aggregate (flag=1). Single aligned 8B store = atomic, no fence needed.
    cb[k * CC + c] =
        (1ULL << 32) | (unsigned long long)__float_as_uint(e);

    // ---- Lookback: start_k = sum_{j<k} A_L^{k-1-j} e_j + A_L^k * y0,
    //      short-circuiting on any published inclusive prefix P_j. ----
    float acc;
    if (k == 0) {
        acc = y0[b * CC + c];
    } else {
        acc = 0.0f;
        float m = 1.0f;
        int j = k - 1;
        bool done = false;
        while (!done) {
            const int g = (j + 1 < 8) ? (j + 1) : 8;
            unsigned long long v[8];
            bool allset;
            do {  // batched spin: 8 independent volatile LDG.64 per round
                allset = true;
#pragma unroll
                for (int u = 0; u < 8; u++) {
                    if (u < g) {
                        v[u] = cb[(j - u) * CC + c];
                        if ((unsigned)(v[u] >> 32) == 0u) allset = false;
                    }
                }
            } while (!allset);
#pragma unroll
            for (int u = 0; u < 8; u++) {
                if (u < g) {
                    const unsigned f  = (unsigned)(v[u] >> 32);
                    const float val   = __uint_as_float((unsigned)(v[u] & 0xFFFFFFFFu));
                    acc = fmaf(m, val, acc);
                    if (f == 2u) { done = true; break; }  // val was inclusive prefix
                    m *= AL;                               // val was aggregate
                }
            }
            if (!done) {
                j -= g;
                if (j < 0) {  // folded all aggregates; add initial state term
                    acc = fmaf(m, y0[b * CC + c], acc);
                    done = true;
                }
            }
        }
    }

    // publish inclusive prefix (flag=2) so later chunks short-circuit
    const float P = fmaf(AL, acc, e);
    cb[k * CC + c] =
        (2ULL << 32) | (unsigned long long)__float_as_uint(P);

    // ---- Phase C: replay recurrence from registers, stream outputs ----
    float y = acc;
    float* op = out + ((b * TT + k * LL) * CC + c);
#pragma unroll
    for (int i = 0; i < LL; i++) {
        y = fmaf(a, y, w * xs[i]);
        __stcs(op + i * CC, y);
    }
}

extern "C" void kernel_launch(void* const* d_in, const int* in_sizes, int n_in,
                              void* d_out, int out_size) {
    const float* x      = (const float*)d_in[0];  // [B, T, C]
    const float* y0     = (const float*)d_in[1];  // [B, C]
    const float* smooth = (const float*)d_in[2];  // [C]
    float* out          = (float*)d_out;          // [B, T, C]

    const int B = in_sizes[0] / (TT * CC);

    // reset carry flags (stream-ordered before the scan; graph-capturable)
    ema_clear_kernel<<<(MAXB * NCH * CC) / 256, 256>>>();
    ema_scan_kernel<<<B * NCH, CC>>>(x, y0, smooth, out);
}